// round 1
// baseline (speedup 1.0000x reference)
#include <cuda_runtime.h>
#include <cstdint>
#include <cstddef>

#define NT 512
#define NG 16384
#define DM 512
#define NH 8
#define DK 64
#define HD 512
#define NGC 256   // NG / 64

// ---------------- scratch (static device memory; no allocations) ----------------
__device__ float  g_K[3][NG][HD];     // K_e[g, h*64+d]      (~100 MB)
__device__ float  g_Q[3][NT][HD];     // Q_e[t, h*64+d]      (~3 MB)
__device__ float  g_U[NH][NT][NG];    // u[h][t][g]          (~268 MB)
__device__ float2 g_part[NH][NT][NGC];// per-gchunk (rowmax, sumexp)
__device__ float2 g_stats[NH][NT];    // (rowmax, 1/Z)

// =====================================================================
// Projection GEMM: C[M,512] = Z[M,512] @ W[512,512]   (3 evidences via blockIdx.z)
// 128x128 CTA tile, BK=16, 256 threads, 8x8 per thread, 1-stage SW pipeline.
// For Q: rows gathered through tf_idx.
// =====================================================================
__global__ __launch_bounds__(256, 2)
void proj_kernel(const float* __restrict__ Za, const float* __restrict__ Zb,
                 const float* __restrict__ Zc,
                 const float* __restrict__ Wa, const float* __restrict__ Wb,
                 const float* __restrict__ Wc,
                 const int* __restrict__ idx, int isQ)
{
    const int e = blockIdx.z;
    const float* Z = (e == 0) ? Za : (e == 1) ? Zb : Zc;
    const float* W = (e == 0) ? Wa : (e == 1) ? Wb : Wc;
    float* C = isQ ? &g_Q[e][0][0] : &g_K[e][0][0];

    __shared__ __align__(16) float As[16][132];  // transposed A: As[k][m]
    __shared__ __align__(16) float Bs[16][128];  // Bs[k][n]

    const int tid = threadIdx.x;
    const int m0 = blockIdx.x * 128;
    const int n0 = blockIdx.y * 128;

    // A loader: thread -> (m = tid/4 and +64, k4 = (tid%4)*4)
    const int am = tid >> 2;
    const int ak = (tid & 3) << 2;
    int ar0 = m0 + am, ar1 = m0 + am + 64;
    if (isQ) { ar0 = idx[ar0]; ar1 = idx[ar1]; }
    const float* Ap0 = Z + (size_t)ar0 * DM + ak;
    const float* Ap1 = Z + (size_t)ar1 * DM + ak;

    // B loader: thread -> (k = tid/32 and +8, n4 = (tid%32)*4)
    const int bn = (tid & 31) << 2;
    const int bk = tid >> 5;
    const float* Bp = W + (size_t)bk * HD + n0 + bn;

    const int ty = tid >> 4, tx = tid & 15;

    float c[8][8];
    #pragma unroll
    for (int i = 0; i < 8; i++)
        #pragma unroll
        for (int j = 0; j < 8; j++) c[i][j] = 0.f;

    // prologue: load k-tile 0
    float4 ra0 = *(const float4*)(Ap0);
    float4 ra1 = *(const float4*)(Ap1);
    float4 rb0 = *(const float4*)(Bp);
    float4 rb1 = *(const float4*)(Bp + (size_t)8 * HD);

    As[ak+0][am]    = ra0.x; As[ak+1][am]    = ra0.y; As[ak+2][am]    = ra0.z; As[ak+3][am]    = ra0.w;
    As[ak+0][am+64] = ra1.x; As[ak+1][am+64] = ra1.y; As[ak+2][am+64] = ra1.z; As[ak+3][am+64] = ra1.w;
    *(float4*)&Bs[bk][bn]     = rb0;
    *(float4*)&Bs[bk+8][bn]   = rb1;
    __syncthreads();

    for (int kt = 0; kt < 32; kt++) {
        float4 na0, na1, nb0, nb1;
        if (kt < 31) {
            const int kn = (kt + 1) * 16;
            na0 = *(const float4*)(Ap0 + kn);
            na1 = *(const float4*)(Ap1 + kn);
            nb0 = *(const float4*)(Bp + (size_t)kn * HD);
            nb1 = *(const float4*)(Bp + (size_t)(kn + 8) * HD);
        }
        #pragma unroll 4
        for (int k = 0; k < 16; k++) {
            float4 a0 = *(const float4*)&As[k][ty * 8];
            float4 a1 = *(const float4*)&As[k][ty * 8 + 4];
            float4 b0 = *(const float4*)&Bs[k][tx * 8];
            float4 b1 = *(const float4*)&Bs[k][tx * 8 + 4];
            const float a[8] = {a0.x, a0.y, a0.z, a0.w, a1.x, a1.y, a1.z, a1.w};
            const float b[8] = {b0.x, b0.y, b0.z, b0.w, b1.x, b1.y, b1.z, b1.w};
            #pragma unroll
            for (int i = 0; i < 8; i++)
                #pragma unroll
                for (int j = 0; j < 8; j++)
                    c[i][j] = fmaf(a[i], b[j], c[i][j]);
        }
        __syncthreads();
        if (kt < 31) {
            As[ak+0][am]    = na0.x; As[ak+1][am]    = na0.y; As[ak+2][am]    = na0.z; As[ak+3][am]    = na0.w;
            As[ak+0][am+64] = na1.x; As[ak+1][am+64] = na1.y; As[ak+2][am+64] = na1.z; As[ak+3][am+64] = na1.w;
            *(float4*)&Bs[bk][bn]   = nb0;
            *(float4*)&Bs[bk+8][bn] = nb1;
            __syncthreads();
        }
    }

    #pragma unroll
    for (int i = 0; i < 8; i++) {
        float* crow = C + (size_t)(m0 + ty * 8 + i) * HD + n0 + tx * 8;
        *(float4*)(crow)     = make_float4(c[i][0], c[i][1], c[i][2], c[i][3]);
        *(float4*)(crow + 4) = make_float4(c[i][4], c[i][5], c[i][6], c[i][7]);
    }
}

// =====================================================================
// Fused scores + evidence gate + partial softmax stats + means.
// CTA = 64 t-rows x 64 g-cols, 256 threads (16x16), 4x4 per thread.
// Loops h=0..7, e=0..2 internally -> no atomics, deterministic.
// Writes: g_U, g_part, u_mean, alpha_mean.
// =====================================================================
__global__ __launch_bounds__(256, 1)
void score_kernel(const float* __restrict__ gateW, const float* __restrict__ gateB,
                  float* __restrict__ out_umean, float* __restrict__ out_amean)
{
    __shared__ float Qs[64][65];
    __shared__ float Ks[64][65];

    const int tid = threadIdx.x;
    const int tx = tid & 15;       // g sub-tile
    const int ty = tid >> 4;       // t sub-tile
    const int t0 = blockIdx.x * 64;
    const int g0 = blockIdx.y * 64;

    float acc_u[16];
    float acc_a[3][16];
    #pragma unroll
    for (int i = 0; i < 16; i++) { acc_u[i] = 0.f; acc_a[0][i] = 0.f; acc_a[1][i] = 0.f; acc_a[2][i] = 0.f; }

    const int lr = tid >> 4;            // load row base (0..15)
    const int lc = (tid & 15) << 2;     // load col (0..60)

    for (int h = 0; h < NH; h++) {
        float s[3][16];
        #pragma unroll 1
        for (int e = 0; e < 3; e++) {
            // stage Q, K tiles (64 x 64 of dim d), scalar stores (2-way conflicts, cheap)
            #pragma unroll
            for (int p = 0; p < 4; p++) {
                const int r = lr + p * 16;
                float4 q = *(const float4*)&g_Q[e][t0 + r][h * DK + lc];
                Qs[r][lc] = q.x; Qs[r][lc+1] = q.y; Qs[r][lc+2] = q.z; Qs[r][lc+3] = q.w;
                float4 kk = *(const float4*)&g_K[e][g0 + r][h * DK + lc];
                Ks[r][lc] = kk.x; Ks[r][lc+1] = kk.y; Ks[r][lc+2] = kk.z; Ks[r][lc+3] = kk.w;
            }
            __syncthreads();

            float acc[16];
            #pragma unroll
            for (int i = 0; i < 16; i++) acc[i] = 0.f;

            #pragma unroll 16
            for (int k = 0; k < 64; k++) {
                float a[4], b[4];
                #pragma unroll
                for (int i = 0; i < 4; i++) a[i] = Qs[ty * 4 + i][k];
                #pragma unroll
                for (int j = 0; j < 4; j++) b[j] = Ks[tx * 4 + j][k];
                #pragma unroll
                for (int i = 0; i < 4; i++)
                    #pragma unroll
                    for (int j = 0; j < 4; j++)
                        acc[i * 4 + j] = fmaf(a[i], b[j], acc[i * 4 + j]);
            }
            #pragma unroll
            for (int i = 0; i < 16; i++) s[e][i] = acc[i] * 0.125f;  // /sqrt(dk)
            __syncthreads();
        }

        // gate params for this head
        const float w00 = gateW[h*9+0], w01 = gateW[h*9+1], w02 = gateW[h*9+2];
        const float w10 = gateW[h*9+3], w11 = gateW[h*9+4], w12 = gateW[h*9+5];
        const float w20 = gateW[h*9+6], w21 = gateW[h*9+7], w22 = gateW[h*9+8];
        const float gb0 = gateB[h*3+0], gb1 = gateB[h*3+1], gb2 = gateB[h*3+2];

        float uarr[16];
        float rmax[4] = {-1e30f, -1e30f, -1e30f, -1e30f};
        #pragma unroll
        for (int r = 0; r < 4; r++) {
            #pragma unroll
            for (int cc = 0; cc < 4; cc++) {
                const int i = r * 4 + cc;
                const float s0 = s[0][i], s1 = s[1][i], s2 = s[2][i];
                float l0 = fmaf(s0, w00, fmaf(s1, w10, fmaf(s2, w20, gb0)));
                float l1 = fmaf(s0, w01, fmaf(s1, w11, fmaf(s2, w21, gb1)));
                float l2 = fmaf(s0, w02, fmaf(s1, w12, fmaf(s2, w22, gb2)));
                const float mx = fmaxf(l0, fmaxf(l1, l2));
                const float e0 = __expf(l0 - mx);
                const float e1 = __expf(l1 - mx);
                const float e2 = __expf(l2 - mx);
                const float inv = 1.0f / (e0 + e1 + e2);
                const float a0 = e0 * inv, a1 = e1 * inv, a2 = e2 * inv;
                const float u = fmaf(a0, s0, fmaf(a1, s1, a2 * s2));
                uarr[i] = u;
                acc_u[i] += u;
                acc_a[0][i] += a0; acc_a[1][i] += a1; acc_a[2][i] += a2;
                rmax[r] = fmaxf(rmax[r], u);
            }
        }

        // per-row (t) reductions across the 16 tx lanes + write u tile
        #pragma unroll
        for (int r = 0; r < 4; r++) {
            float m = rmax[r];
            #pragma unroll
            for (int off = 8; off; off >>= 1)
                m = fmaxf(m, __shfl_xor_sync(0xffffffffu, m, off, 16));
            float zs = 0.f;
            #pragma unroll
            for (int cc = 0; cc < 4; cc++) zs += __expf(uarr[r * 4 + cc] - m);
            #pragma unroll
            for (int off = 8; off; off >>= 1)
                zs += __shfl_xor_sync(0xffffffffu, zs, off, 16);
            const int t = t0 + ty * 4 + r;
            if (tx == 0) g_part[h][t][blockIdx.y] = make_float2(m, zs);
            *(float4*)&g_U[h][t][g0 + tx * 4] =
                make_float4(uarr[r*4], uarr[r*4+1], uarr[r*4+2], uarr[r*4+3]);
        }
    }

    // write mean outputs (each element owned by exactly one thread)
    #pragma unroll
    for (int r = 0; r < 4; r++) {
        const int t = t0 + ty * 4 + r;
        const int g = g0 + tx * 4;
        *(float4*)(out_umean + (size_t)t * NG + g) =
            make_float4(acc_u[r*4]*0.125f, acc_u[r*4+1]*0.125f, acc_u[r*4+2]*0.125f, acc_u[r*4+3]*0.125f);
        float av[12];
        #pragma unroll
        for (int cc = 0; cc < 4; cc++)
            #pragma unroll
            for (int f = 0; f < 3; f++)
                av[cc * 3 + f] = acc_a[f][r * 4 + cc] * 0.125f;
        float4* ap = (float4*)(out_amean + ((size_t)t * NG + g) * 3);
        ap[0] = make_float4(av[0], av[1], av[2],  av[3]);
        ap[1] = make_float4(av[4], av[5], av[6],  av[7]);
        ap[2] = make_float4(av[8], av[9], av[10], av[11]);
    }
}

// =====================================================================
// Reduce per-chunk partials -> global (max, 1/Z) per (h, t). One warp per row.
// =====================================================================
__global__ void stats_kernel()
{
    const int gt   = blockIdx.x * blockDim.x + threadIdx.x;
    const int wid  = gt >> 5;
    const int lane = threadIdx.x & 31;
    if (wid >= NH * NT) return;
    const int h = wid >> 9;
    const int t = wid & (NT - 1);

    float2 p[8];
    float m = -1e30f;
    #pragma unroll
    for (int j = 0; j < 8; j++) {
        p[j] = g_part[h][t][lane + 32 * j];
        m = fmaxf(m, p[j].x);
    }
    #pragma unroll
    for (int off = 16; off; off >>= 1)
        m = fmaxf(m, __shfl_xor_sync(0xffffffffu, m, off));
    float z = 0.f;
    #pragma unroll
    for (int j = 0; j < 8; j++) z += p[j].y * __expf(p[j].x - m);
    #pragma unroll
    for (int off = 16; off; off >>= 1)
        z += __shfl_xor_sync(0xffffffffu, z, off);
    if (lane == 0) g_stats[h][t] = make_float2(m, 1.0f / z);
}

// =====================================================================
// A_mean[t,g] = (1/8) * sum_h exp(u[h,t,g] - m[h,t]) / Z[h,t]
// =====================================================================
__global__ void amean_kernel(float* __restrict__ out_A)
{
    const int t = blockIdx.y;
    const int g = blockIdx.x * 256 + threadIdx.x;
    __shared__ float2 st[NH];
    if (threadIdx.x < NH) st[threadIdx.x] = g_stats[threadIdx.x][t];
    __syncthreads();
    float acc = 0.f;
    #pragma unroll
    for (int h = 0; h < NH; h++)
        acc += __expf(g_U[h][t][g] - st[h].x) * st[h].y;
    out_A[(size_t)t * NG + g] = acc * 0.125f;
}

// =====================================================================
// Passthrough copies of H_TF and H_G into the output buffer.
// =====================================================================
__global__ void copy_kernel(const float4* __restrict__ a, const float4* __restrict__ b,
                            float4* __restrict__ out)
{
    const int NA   = (NT * DM) / 4;               // 65536
    const int NTOT = NA + (NG * DM) / 4;          // 2162688
    for (int i = blockIdx.x * blockDim.x + threadIdx.x; i < NTOT; i += gridDim.x * blockDim.x)
        out[i] = (i < NA) ? a[i] : b[i - NA];
}

// =====================================================================
extern "C" void kernel_launch(void* const* d_in, const int* in_sizes, int n_in,
                              void* d_out, int out_size)
{
    const float* H_TF   = (const float*)d_in[0];
    const float* H_G    = (const float*)d_in[1];
    const float* z_exp  = (const float*)d_in[2];
    const float* z_seq  = (const float*)d_in[3];
    const float* z_txt  = (const float*)d_in[4];
    const int*   tf_idx = (const int*)  d_in[5];
    const float* Wq_seq = (const float*)d_in[6];
    const float* Wk_seq = (const float*)d_in[7];
    const float* Wq_exp = (const float*)d_in[8];
    const float* Wk_exp = (const float*)d_in[9];
    const float* Wq_txt = (const float*)d_in[10];
    const float* Wk_txt = (const float*)d_in[11];
    const float* gateW  = (const float*)d_in[12];
    const float* gateB  = (const float*)d_in[13];
    float* out = (float*)d_out;

    // output layout: H_TF | H_G | A_mean | u_mean | alpha_mean
    float* out_A  = out + (size_t)NT * DM + (size_t)NG * DM;     // 8650752
    float* out_u  = out_A + (size_t)NT * NG;                      // +8388608
    float* out_al = out_u + (size_t)NT * NG;                      // +8388608

    // evidence order matches stack([s_bind, s_coexpr, s_know]):
    //   e0 = seq, e1 = exp, e2 = txt
    dim3 gK(NG / 128, HD / 128, 3);
    proj_kernel<<<gK, 256>>>(z_seq, z_exp, z_txt, Wk_seq, Wk_exp, Wk_txt, nullptr, 0);
    dim3 gQ(NT / 128, HD / 128, 3);
    proj_kernel<<<gQ, 256>>>(z_seq, z_exp, z_txt, Wq_seq, Wq_exp, Wq_txt, tf_idx, 1);

    dim3 gS(NT / 64, NG / 64);
    score_kernel<<<gS, 256>>>(gateW, gateB, out_u, out_al);

    stats_kernel<<<(NH * NT * 32) / 256, 256>>>();

    amean_kernel<<<dim3(NG / 256, NT), 256>>>(out_A);

    copy_kernel<<<2048, 256>>>((const float4*)H_TF, (const float4*)H_G, (float4*)out);
}

// round 2
// speedup vs baseline: 1.6003x; 1.6003x over previous
#include <cuda_runtime.h>
#include <cuda_bf16.h>
#include <cstdint>
#include <cstddef>

#define NT 512
#define NG 16384
#define DM 512
#define NH 8
#define DK 64
#define HD 512
#define NGC 256   // NG / 64

typedef __nv_bfloat16 bf16;
typedef __nv_bfloat162 bf162;

// ---------------- scratch (static device memory) ----------------
__device__ bf16  g_Zh[3][NG][DM], g_Zl[3][NG][DM];   // split inputs
__device__ bf16  g_Wh[6][DM][HD], g_Wl[6][DM][HD];   // 0-2: Wk_{seq,exp,txt}, 3-5: Wq_*
__device__ bf16  g_Qh[3][NT][HD], g_Ql[3][NT][HD];
__device__ bf16  g_Kh[3][NG][HD], g_Kl[3][NG][HD];
__device__ float g_U[NH][NT][NG];                    // u scores (fp32)
__device__ float2 g_part[NH][NT][NGC];
__device__ float2 g_stats[NH][NT];

// ---------------- ptx helpers ----------------
__device__ __forceinline__ uint32_t s2u(const void* p) {
    return (uint32_t)__cvta_generic_to_shared(p);
}
__device__ __forceinline__ void ldsm4(uint32_t* r, uint32_t a) {
    asm volatile("ldmatrix.sync.aligned.m8n8.x4.shared.b16 {%0,%1,%2,%3},[%4];\n"
                 : "=r"(r[0]), "=r"(r[1]), "=r"(r[2]), "=r"(r[3]) : "r"(a));
}
__device__ __forceinline__ void ldsm4t(uint32_t* r, uint32_t a) {
    asm volatile("ldmatrix.sync.aligned.m8n8.x4.trans.shared.b16 {%0,%1,%2,%3},[%4];\n"
                 : "=r"(r[0]), "=r"(r[1]), "=r"(r[2]), "=r"(r[3]) : "r"(a));
}
__device__ __forceinline__ void mma_bf16(float* d, const uint32_t* a, const uint32_t* b) {
    asm volatile("mma.sync.aligned.m16n8k16.row.col.f32.bf16.bf16.f32 "
                 "{%0,%1,%2,%3},{%4,%5,%6,%7},{%8,%9},{%0,%1,%2,%3};\n"
                 : "+f"(d[0]), "+f"(d[1]), "+f"(d[2]), "+f"(d[3])
                 : "r"(a[0]), "r"(a[1]), "r"(a[2]), "r"(a[3]), "r"(b[0]), "r"(b[1]));
}

// =====================================================================
// Split fp32 -> bf16 hi/lo pairs for z (3) and W (6).
// =====================================================================
__global__ void split_kernel(const float4* __restrict__ za, const float4* __restrict__ zb,
                             const float4* __restrict__ zc,
                             const float4* __restrict__ w0, const float4* __restrict__ w1,
                             const float4* __restrict__ w2, const float4* __restrict__ w3,
                             const float4* __restrict__ w4, const float4* __restrict__ w5)
{
    const int NZ4 = NG * DM / 4;
    const int NW4 = DM * HD / 4;
    const int TOT = 3 * NZ4 + 6 * NW4;
    for (int i = blockIdx.x * blockDim.x + threadIdx.x; i < TOT; i += gridDim.x * blockDim.x) {
        float4 v; bf162 *dh, *dl;
        if (i < 3 * NZ4) {
            const int e = i / NZ4, j = i - e * NZ4;
            v = (e == 0 ? za : e == 1 ? zb : zc)[j];
            dh = (bf162*)&g_Zh[e][0][0] + (size_t)j * 2;
            dl = (bf162*)&g_Zl[e][0][0] + (size_t)j * 2;
        } else {
            const int k = i - 3 * NZ4;
            const int w = k / NW4, j = k - w * NW4;
            const float4* src = w == 0 ? w0 : w == 1 ? w1 : w == 2 ? w2 : w == 3 ? w3 : w == 4 ? w4 : w5;
            v = src[j];
            dh = (bf162*)&g_Wh[w][0][0] + (size_t)j * 2;
            dl = (bf162*)&g_Wl[w][0][0] + (size_t)j * 2;
        }
        bf16 hx = __float2bfloat16(v.x), hy = __float2bfloat16(v.y);
        bf16 hz = __float2bfloat16(v.z), hw = __float2bfloat16(v.w);
        bf162 p0; p0.x = hx; p0.y = hy;
        bf162 p1; p1.x = hz; p1.y = hw;
        dh[0] = p0; dh[1] = p1;
        bf162 q0; q0.x = __float2bfloat16(v.x - __bfloat162float(hx));
                  q0.y = __float2bfloat16(v.y - __bfloat162float(hy));
        bf162 q1; q1.x = __float2bfloat16(v.z - __bfloat162float(hz));
                  q1.y = __float2bfloat16(v.w - __bfloat162float(hw));
        dl[0] = q0; dl[1] = q1;
    }
}

// =====================================================================
// Projection GEMM via bf16-split MMA: C[M,512] = Z[M,512] @ W[512,512]
// CTA 128x128, BK=32, 256 threads (8 warps, 2x4), warp 64x32.
// Output written as bf16 hi/lo pairs directly.
// =====================================================================
__global__ __launch_bounds__(256, 1)
void proj_mma(const int* __restrict__ idx, int isQ)
{
    const int e = blockIdx.z;
    const int m0 = blockIdx.x * 128, n0 = blockIdx.y * 128;
    const bf16* Zh = &g_Zh[e][0][0];
    const bf16* Zl = &g_Zl[e][0][0];
    const int widx = (isQ ? 3 : 0) + e;
    const bf16* Wh = &g_Wh[widx][0][0];
    const bf16* Wl = &g_Wl[widx][0][0];
    bf16* Ch = isQ ? &g_Qh[e][0][0] : &g_Kh[e][0][0];
    bf16* Cl = isQ ? &g_Ql[e][0][0] : &g_Kl[e][0][0];

    extern __shared__ char sm[];
    const int ASZ = 128 * 40;   // elements per A buffer
    const int BSZ = 32 * 136;
    bf16* sAh = (bf16*)sm;            // [2][ASZ]
    bf16* sAl = sAh + 2 * ASZ;
    bf16* sBh = sAl + 2 * ASZ;        // [2][BSZ]
    bf16* sBl = sBh + 2 * BSZ;

    const int tid = threadIdx.x;
    const int lane = tid & 31, warp = tid >> 5;
    const int wm = warp >> 2, wn = warp & 3;

    // loader indices
    const int l0 = tid, l1 = tid + 256;
    const int ar0 = l0 >> 2, ac0 = (l0 & 3) << 3;
    const int ar1 = l1 >> 2, ac1 = (l1 & 3) << 3;
    const int gr0 = isQ ? idx[m0 + ar0] : (m0 + ar0);
    const int gr1 = isQ ? idx[m0 + ar1] : (m0 + ar1);
    const bf16* pAh0 = Zh + (size_t)gr0 * DM + ac0;
    const bf16* pAh1 = Zh + (size_t)gr1 * DM + ac1;
    const bf16* pAl0 = Zl + (size_t)gr0 * DM + ac0;
    const bf16* pAl1 = Zl + (size_t)gr1 * DM + ac1;

    const int br0 = l0 >> 4, bc0 = (l0 & 15) << 3;
    const int br1 = l1 >> 4, bc1 = (l1 & 15) << 3;
    const bf16* pBh0 = Wh + (size_t)br0 * HD + n0 + bc0;
    const bf16* pBh1 = Wh + (size_t)br1 * HD + n0 + bc1;
    const bf16* pBl0 = Wl + (size_t)br0 * HD + n0 + bc0;
    const bf16* pBl1 = Wl + (size_t)br1 * HD + n0 + bc1;

    float acc[4][4][4];
    #pragma unroll
    for (int i = 0; i < 4; i++)
        #pragma unroll
        for (int j = 0; j < 4; j++)
            #pragma unroll
            for (int k = 0; k < 4; k++) acc[i][j][k] = 0.f;

    // prologue: k-tile 0 into buffer 0
    {
        *(uint4*)&sAh[ar0 * 40 + ac0] = *(const uint4*)(pAh0);
        *(uint4*)&sAh[ar1 * 40 + ac1] = *(const uint4*)(pAh1);
        *(uint4*)&sAl[ar0 * 40 + ac0] = *(const uint4*)(pAl0);
        *(uint4*)&sAl[ar1 * 40 + ac1] = *(const uint4*)(pAl1);
        *(uint4*)&sBh[br0 * 136 + bc0] = *(const uint4*)(pBh0);
        *(uint4*)&sBh[br1 * 136 + bc1] = *(const uint4*)(pBh1);
        *(uint4*)&sBl[br0 * 136 + bc0] = *(const uint4*)(pBl0);
        *(uint4*)&sBl[br1 * 136 + bc1] = *(const uint4*)(pBl1);
    }
    __syncthreads();

    int cur = 0;
    for (int kt = 0; kt < 16; kt++) {
        uint4 nAh0, nAh1, nAl0, nAl1, nBh0, nBh1, nBl0, nBl1;
        if (kt < 15) {
            const int k0 = (kt + 1) * 32;
            nAh0 = *(const uint4*)(pAh0 + k0);
            nAh1 = *(const uint4*)(pAh1 + k0);
            nAl0 = *(const uint4*)(pAl0 + k0);
            nAl1 = *(const uint4*)(pAl1 + k0);
            nBh0 = *(const uint4*)(pBh0 + (size_t)k0 * HD);
            nBh1 = *(const uint4*)(pBh1 + (size_t)k0 * HD);
            nBl0 = *(const uint4*)(pBl0 + (size_t)k0 * HD);
            nBl1 = *(const uint4*)(pBl1 + (size_t)k0 * HD);
        }

        const bf16* cAh = sAh + cur * ASZ;
        const bf16* cAl = sAl + cur * ASZ;
        const bf16* cBh = sBh + cur * BSZ;
        const bf16* cBl = sBl + cur * BSZ;

        #pragma unroll
        for (int kk = 0; kk < 32; kk += 16) {
            uint32_t ah[4][4], al[4][4], bh[4][2], bl[4][2];
            #pragma unroll
            for (int mi = 0; mi < 4; mi++) {
                const int row = wm * 64 + mi * 16 + (lane & 15);
                const int col = kk + ((lane >> 4) << 3);
                ldsm4(ah[mi], s2u(&cAh[row * 40 + col]));
                ldsm4(al[mi], s2u(&cAl[row * 40 + col]));
            }
            #pragma unroll
            for (int n16 = 0; n16 < 2; n16++) {
                const int row = kk + (lane & 15);
                const int col = wn * 32 + n16 * 16 + ((lane >> 4) << 3);
                uint32_t th[4], tl[4];
                ldsm4t(th, s2u(&cBh[row * 136 + col]));
                ldsm4t(tl, s2u(&cBl[row * 136 + col]));
                bh[n16 * 2 + 0][0] = th[0]; bh[n16 * 2 + 0][1] = th[1];
                bh[n16 * 2 + 1][0] = th[2]; bh[n16 * 2 + 1][1] = th[3];
                bl[n16 * 2 + 0][0] = tl[0]; bl[n16 * 2 + 0][1] = tl[1];
                bl[n16 * 2 + 1][0] = tl[2]; bl[n16 * 2 + 1][1] = tl[3];
            }
            #pragma unroll
            for (int mi = 0; mi < 4; mi++)
                #pragma unroll
                for (int nf = 0; nf < 4; nf++) {
                    mma_bf16(acc[mi][nf], ah[mi], bh[nf]);
                    mma_bf16(acc[mi][nf], ah[mi], bl[nf]);
                    mma_bf16(acc[mi][nf], al[mi], bh[nf]);
                }
        }

        if (kt < 15) {
            const int nb = cur ^ 1;
            *(uint4*)&sAh[nb * ASZ + ar0 * 40 + ac0] = nAh0;
            *(uint4*)&sAh[nb * ASZ + ar1 * 40 + ac1] = nAh1;
            *(uint4*)&sAl[nb * ASZ + ar0 * 40 + ac0] = nAl0;
            *(uint4*)&sAl[nb * ASZ + ar1 * 40 + ac1] = nAl1;
            *(uint4*)&sBh[nb * BSZ + br0 * 136 + bc0] = nBh0;
            *(uint4*)&sBh[nb * BSZ + br1 * 136 + bc1] = nBh1;
            *(uint4*)&sBl[nb * BSZ + br0 * 136 + bc0] = nBl0;
            *(uint4*)&sBl[nb * BSZ + br1 * 136 + bc1] = nBl1;
            __syncthreads();
            cur ^= 1;
        }
    }

    // epilogue: split fp32 acc -> bf16 hi/lo stores
    #pragma unroll
    for (int mi = 0; mi < 4; mi++) {
        const int r0 = m0 + wm * 64 + mi * 16 + (lane >> 2);
        #pragma unroll
        for (int nf = 0; nf < 4; nf++) {
            const int cc = n0 + wn * 32 + nf * 8 + ((lane & 3) << 1);
            #pragma unroll
            for (int rh = 0; rh < 2; rh++) {
                const int r = r0 + rh * 8;
                const float x0 = acc[mi][nf][rh * 2 + 0];
                const float x1 = acc[mi][nf][rh * 2 + 1];
                bf162 hp; hp.x = __float2bfloat16(x0); hp.y = __float2bfloat16(x1);
                bf162 lp; lp.x = __float2bfloat16(x0 - __bfloat162float(hp.x));
                          lp.y = __float2bfloat16(x1 - __bfloat162float(hp.y));
                *(bf162*)&Ch[(size_t)r * HD + cc] = hp;
                *(bf162*)&Cl[(size_t)r * HD + cc] = lp;
            }
        }
    }
}

// =====================================================================
// Fused scores (MMA) + gate + partial softmax stats + means.
// CTA 64t x 64g, 256 threads (8 warps, 2x4), warp 32x16.
// =====================================================================
__global__ __launch_bounds__(256, 1)
void score_mma(const float* __restrict__ gateW, const float* __restrict__ gateB,
               float* __restrict__ out_umean, float* __restrict__ out_amean)
{
    extern __shared__ char sm[];
    const int TSZ = 64 * 72;
    bf16* sQh = (bf16*)sm;
    bf16* sQl = sQh + TSZ;
    bf16* sKh = sQl + TSZ;
    bf16* sKl = sKh + TSZ;
    float* accU = (float*)(sm + 36864);        // [64][65]
    float* accA = accU + 64 * 65;              // [3][64][65]
    float2* part = (float2*)(accA + 3 * 64 * 65); // [64][4]

    const int tid = threadIdx.x;
    const int lane = tid & 31, warp = tid >> 5;
    const int wt = warp >> 2, wg = warp & 3;
    const int t0 = blockIdx.x * 64;
    const int g0 = blockIdx.y * 64;

    // zero accumulators
    for (int i = tid; i < 64 * 65; i += 256) {
        accU[i] = 0.f; accA[i] = 0.f; accA[64 * 65 + i] = 0.f; accA[2 * 64 * 65 + i] = 0.f;
    }
    __syncthreads();

    for (int h = 0; h < NH; h++) {
        float s[3][2][2][4];
        #pragma unroll
        for (int e = 0; e < 3; e++)
            #pragma unroll
            for (int a = 0; a < 2; a++)
                #pragma unroll
                for (int b = 0; b < 2; b++)
                    #pragma unroll
                    for (int k = 0; k < 4; k++) s[e][a][b][k] = 0.f;

        #pragma unroll 1
        for (int e = 0; e < 3; e++) {
            __syncthreads();   // protect previous tiles / partials
            {
                const bf16* Qh = &g_Qh[e][0][0]; const bf16* Ql = &g_Ql[e][0][0];
                const bf16* Kh = &g_Kh[e][0][0]; const bf16* Kl = &g_Kl[e][0][0];
                #pragma unroll
                for (int j = 0; j < 2; j++) {
                    const int lin = tid + j * 256;
                    const int row = lin >> 3, c8 = (lin & 7) << 3;
                    const size_t go = (size_t)(t0 + row) * HD + h * DK + c8;
                    *(uint4*)&sQh[row * 72 + c8] = *(const uint4*)&Qh[go];
                    *(uint4*)&sQl[row * 72 + c8] = *(const uint4*)&Ql[go];
                    const size_t gk = (size_t)(g0 + row) * HD + h * DK + c8;
                    *(uint4*)&sKh[row * 72 + c8] = *(const uint4*)&Kh[gk];
                    *(uint4*)&sKl[row * 72 + c8] = *(const uint4*)&Kl[gk];
                }
            }
            __syncthreads();

            #pragma unroll
            for (int kk = 0; kk < 64; kk += 16) {
                uint32_t ah[2][4], al[2][4];
                #pragma unroll
                for (int mi = 0; mi < 2; mi++) {
                    const int row = wt * 32 + mi * 16 + (lane & 15);
                    const int col = kk + ((lane >> 4) << 3);
                    ldsm4(ah[mi], s2u(&sQh[row * 72 + col]));
                    ldsm4(al[mi], s2u(&sQl[row * 72 + col]));
                }
                uint32_t krh[4], krl[4];
                {
                    const int row = wg * 16 + (lane & 15);
                    const int col = kk + ((lane >> 4) << 3);
                    ldsm4(krh, s2u(&sKh[row * 72 + col]));
                    ldsm4(krl, s2u(&sKl[row * 72 + col]));
                }
                uint32_t bh[2][2] = {{krh[0], krh[2]}, {krh[1], krh[3]}};
                uint32_t bl[2][2] = {{krl[0], krl[2]}, {krl[1], krl[3]}};
                #pragma unroll
                for (int mi = 0; mi < 2; mi++)
                    #pragma unroll
                    for (int nf = 0; nf < 2; nf++) {
                        mma_bf16(s[e][mi][nf], ah[mi], bh[nf]);
                        mma_bf16(s[e][mi][nf], ah[mi], bl[nf]);
                        mma_bf16(s[e][mi][nf], al[mi], bh[nf]);
                    }
            }
        }

        // ---- gate + softmax-stats epilogue ----
        const float w00 = gateW[h*9+0], w01 = gateW[h*9+1], w02 = gateW[h*9+2];
        const float w10 = gateW[h*9+3], w11 = gateW[h*9+4], w12 = gateW[h*9+5];
        const float w20 = gateW[h*9+6], w21 = gateW[h*9+7], w22 = gateW[h*9+8];
        const float gb0 = gateB[h*3+0], gb1 = gateB[h*3+1], gb2 = gateB[h*3+2];

        #pragma unroll
        for (int mi = 0; mi < 2; mi++) {
            #pragma unroll
            for (int rh = 0; rh < 2; rh++) {
                const int tl = wt * 32 + mi * 16 + (lane >> 2) + rh * 8;
                float uv[2][2];
                float um = -1e30f;
                #pragma unroll
                for (int nf = 0; nf < 2; nf++) {
                    #pragma unroll
                    for (int p = 0; p < 2; p++) {
                        const float s0 = s[0][mi][nf][rh * 2 + p] * 0.125f;
                        const float s1 = s[1][mi][nf][rh * 2 + p] * 0.125f;
                        const float s2 = s[2][mi][nf][rh * 2 + p] * 0.125f;
                        float l0 = fmaf(s0, w00, fmaf(s1, w10, fmaf(s2, w20, gb0)));
                        float l1 = fmaf(s0, w01, fmaf(s1, w11, fmaf(s2, w21, gb1)));
                        float l2 = fmaf(s0, w02, fmaf(s1, w12, fmaf(s2, w22, gb2)));
                        const float mx = fmaxf(l0, fmaxf(l1, l2));
                        const float e0 = __expf(l0 - mx);
                        const float e1 = __expf(l1 - mx);
                        const float e2 = __expf(l2 - mx);
                        const float inv = 1.0f / (e0 + e1 + e2);
                        const float a0 = e0 * inv, a1 = e1 * inv, a2 = e2 * inv;
                        const float u = fmaf(a0, s0, fmaf(a1, s1, a2 * s2));
                        uv[nf][p] = u;
                        const int gl = wg * 16 + nf * 8 + ((lane & 3) << 1) + p;
                        accU[tl * 65 + gl] += u;
                        accA[tl * 65 + gl] += a0;
                        accA[64 * 65 + tl * 65 + gl] += a1;
                        accA[2 * 64 * 65 + tl * 65 + gl] += a2;
                        um = fmaxf(um, u);
                    }
                }
                // row reduction across quad (16 g-cols of this warp)
                um = fmaxf(um, __shfl_xor_sync(0xffffffffu, um, 1));
                um = fmaxf(um, __shfl_xor_sync(0xffffffffu, um, 2));
                float zs = __expf(uv[0][0] - um) + __expf(uv[0][1] - um)
                         + __expf(uv[1][0] - um) + __expf(uv[1][1] - um);
                zs += __shfl_xor_sync(0xffffffffu, zs, 1);
                zs += __shfl_xor_sync(0xffffffffu, zs, 2);
                if ((lane & 3) == 0) part[tl * 4 + wg] = make_float2(um, zs);
                #pragma unroll
                for (int nf = 0; nf < 2; nf++) {
                    float2 st; st.x = uv[nf][0]; st.y = uv[nf][1];
                    *(float2*)&g_U[h][t0 + tl][g0 + wg * 16 + nf * 8 + ((lane & 3) << 1)] = st;
                }
            }
        }
        __syncthreads();
        if (tid < 64) {
            float2 p0 = part[tid * 4 + 0], p1 = part[tid * 4 + 1];
            float2 p2 = part[tid * 4 + 2], p3 = part[tid * 4 + 3];
            float m = fmaxf(fmaxf(p0.x, p1.x), fmaxf(p2.x, p3.x));
            float z = p0.y * __expf(p0.x - m) + p1.y * __expf(p1.x - m)
                    + p2.y * __expf(p2.x - m) + p3.y * __expf(p3.x - m);
            g_part[h][t0 + tid][blockIdx.y] = make_float2(m, z);
        }
    }

    __syncthreads();
    // write means
    for (int i = tid; i < 64 * 64; i += 256) {
        const int r = i >> 6, c = i & 63;
        const size_t o = (size_t)(t0 + r) * NG + g0 + c;
        out_umean[o] = accU[r * 65 + c] * 0.125f;
        out_amean[o * 3 + 0] = accA[r * 65 + c] * 0.125f;
        out_amean[o * 3 + 1] = accA[64 * 65 + r * 65 + c] * 0.125f;
        out_amean[o * 3 + 2] = accA[2 * 64 * 65 + r * 65 + c] * 0.125f;
    }
}

// =====================================================================
// Reduce per-chunk partials -> global (max, 1/Z) per (h, t).
// =====================================================================
__global__ void stats_kernel()
{
    const int gt   = blockIdx.x * blockDim.x + threadIdx.x;
    const int wid  = gt >> 5;
    const int lane = threadIdx.x & 31;
    if (wid >= NH * NT) return;
    const int h = wid >> 9;
    const int t = wid & (NT - 1);

    float2 p[8];
    float m = -1e30f;
    #pragma unroll
    for (int j = 0; j < 8; j++) {
        p[j] = g_part[h][t][lane + 32 * j];
        m = fmaxf(m, p[j].x);
    }
    #pragma unroll
    for (int off = 16; off; off >>= 1)
        m = fmaxf(m, __shfl_xor_sync(0xffffffffu, m, off));
    float z = 0.f;
    #pragma unroll
    for (int j = 0; j < 8; j++) z += p[j].y * __expf(p[j].x - m);
    #pragma unroll
    for (int off = 16; off; off >>= 1)
        z += __shfl_xor_sync(0xffffffffu, z, off);
    if (lane == 0) g_stats[h][t] = make_float2(m, 1.0f / z);
}

// =====================================================================
// A_mean[t,g] = (1/8) * sum_h exp(u[h,t,g] - m[h,t]) / Z[h,t]
// =====================================================================
__global__ void amean_kernel(float* __restrict__ out_A)
{
    const int t = blockIdx.y;
    const int g = blockIdx.x * 256 + threadIdx.x;
    __shared__ float2 st[NH];
    if (threadIdx.x < NH) st[threadIdx.x] = g_stats[threadIdx.x][t];
    __syncthreads();
    float acc = 0.f;
    #pragma unroll
    for (int h = 0; h < NH; h++)
        acc += __expf(g_U[h][t][g] - st[h].x) * st[h].y;
    out_A[(size_t)t * NG + g] = acc * 0.125f;
}

// =====================================================================
__global__ void copy_kernel(const float4* __restrict__ a, const float4* __restrict__ b,
                            float4* __restrict__ out)
{
    const int NA   = (NT * DM) / 4;
    const int NTOT = NA + (NG * DM) / 4;
    for (int i = blockIdx.x * blockDim.x + threadIdx.x; i < NTOT; i += gridDim.x * blockDim.x)
        out[i] = (i < NA) ? a[i] : b[i - NA];
}

// =====================================================================
extern "C" void kernel_launch(void* const* d_in, const int* in_sizes, int n_in,
                              void* d_out, int out_size)
{
    const float* H_TF   = (const float*)d_in[0];
    const float* H_G    = (const float*)d_in[1];
    const float* z_exp  = (const float*)d_in[2];
    const float* z_seq  = (const float*)d_in[3];
    const float* z_txt  = (const float*)d_in[4];
    const int*   tf_idx = (const int*)  d_in[5];
    const float* Wq_seq = (const float*)d_in[6];
    const float* Wk_seq = (const float*)d_in[7];
    const float* Wq_exp = (const float*)d_in[8];
    const float* Wk_exp = (const float*)d_in[9];
    const float* Wq_txt = (const float*)d_in[10];
    const float* Wk_txt = (const float*)d_in[11];
    const float* gateW  = (const float*)d_in[12];
    const float* gateB  = (const float*)d_in[13];
    float* out = (float*)d_out;

    float* out_A  = out + (size_t)NT * DM + (size_t)NG * DM;
    float* out_u  = out_A + (size_t)NT * NG;
    float* out_al = out_u + (size_t)NT * NG;

    cudaFuncSetAttribute(proj_mma, cudaFuncAttributeMaxDynamicSharedMemorySize, 75776);
    cudaFuncSetAttribute(score_mma, cudaFuncAttributeMaxDynamicSharedMemorySize, 105472);

    // evidence order: e0 = seq (bind), e1 = exp (coexpr), e2 = txt (know)
    split_kernel<<<4096, 256>>>((const float4*)z_seq, (const float4*)z_exp, (const float4*)z_txt,
                                (const float4*)Wk_seq, (const float4*)Wk_exp, (const float4*)Wk_txt,
                                (const float4*)Wq_seq, (const float4*)Wq_exp, (const float4*)Wq_txt);

    proj_mma<<<dim3(NG / 128, 4, 3), 256, 75776>>>(nullptr, 0);
    proj_mma<<<dim3(NT / 128, 4, 3), 256, 75776>>>(tf_idx, 1);

    score_mma<<<dim3(NT / 64, NG / 64), 256, 105472>>>(gateW, gateB, out_u, out_al);

    stats_kernel<<<(NH * NT * 32) / 256, 256>>>();

    amean_kernel<<<dim3(NG / 256, NT), 256>>>(out_A);

    copy_kernel<<<2048, 256>>>((const float4*)H_TF, (const float4*)H_G, (float4*)out);
}

// round 4
// speedup vs baseline: 2.2936x; 1.4332x over previous
#include <cuda_runtime.h>
#include <cuda_bf16.h>
#include <cstdint>
#include <cstddef>

#define NT 512
#define NG 16384
#define DM 512
#define NH 8
#define DK 64
#define HD 512
#define NGC 256   // NG / 64

typedef __nv_bfloat16 bf16;
typedef __nv_bfloat162 bf162;

// ---------------- scratch (static device memory) ----------------
__device__ bf16  g_Zh[3][NG][DM], g_Zl[3][NG][DM];   // split inputs
__device__ bf16  g_Wh[6][DM][HD], g_Wl[6][DM][HD];   // 0-2: Wk_{seq,exp,txt}, 3-5: Wq_*
__device__ bf16  g_Qh[3][NT][HD], g_Ql[3][NT][HD];
__device__ bf16  g_Kh[3][NG][HD], g_Kl[3][NG][HD];
__device__ float g_U[NH][NT][NG];                    // u scores (fp32)
__device__ float2 g_part[NH][NT][NGC];
__device__ float2 g_stats[NH][NT];

// ---------------- ptx helpers ----------------
__device__ __forceinline__ uint32_t s2u(const void* p) {
    return (uint32_t)__cvta_generic_to_shared(p);
}
__device__ __forceinline__ void ldsm4(uint32_t* r, uint32_t a) {
    asm volatile("ldmatrix.sync.aligned.m8n8.x4.shared.b16 {%0,%1,%2,%3},[%4];\n"
                 : "=r"(r[0]), "=r"(r[1]), "=r"(r[2]), "=r"(r[3]) : "r"(a));
}
__device__ __forceinline__ void ldsm4t(uint32_t* r, uint32_t a) {
    asm volatile("ldmatrix.sync.aligned.m8n8.x4.trans.shared.b16 {%0,%1,%2,%3},[%4];\n"
                 : "=r"(r[0]), "=r"(r[1]), "=r"(r[2]), "=r"(r[3]) : "r"(a));
}
__device__ __forceinline__ void mma_bf16(float* d, const uint32_t* a, const uint32_t* b) {
    asm volatile("mma.sync.aligned.m16n8k16.row.col.f32.bf16.bf16.f32 "
                 "{%0,%1,%2,%3},{%4,%5,%6,%7},{%8,%9},{%0,%1,%2,%3};\n"
                 : "+f"(d[0]), "+f"(d[1]), "+f"(d[2]), "+f"(d[3])
                 : "r"(a[0]), "r"(a[1]), "r"(a[2]), "r"(a[3]), "r"(b[0]), "r"(b[1]));
}
__device__ __forceinline__ void cpa16(uint32_t s, const void* g) {
    asm volatile("cp.async.cg.shared.global [%0], [%1], 16;\n" :: "r"(s), "l"(g) : "memory");
}
#define CP_COMMIT() asm volatile("cp.async.commit_group;\n" ::: "memory")
#define CP_WAIT0()  asm volatile("cp.async.wait_group 0;\n" ::: "memory")

// =====================================================================
// Split fp32 -> bf16 hi/lo pairs for z (3) and W (6).
// =====================================================================
__global__ void split_kernel(const float4* __restrict__ za, const float4* __restrict__ zb,
                             const float4* __restrict__ zc,
                             const float4* __restrict__ w0, const float4* __restrict__ w1,
                             const float4* __restrict__ w2, const float4* __restrict__ w3,
                             const float4* __restrict__ w4, const float4* __restrict__ w5)
{
    const int NZ4 = NG * DM / 4;
    const int NW4 = DM * HD / 4;
    const int TOT = 3 * NZ4 + 6 * NW4;
    for (int i = blockIdx.x * blockDim.x + threadIdx.x; i < TOT; i += gridDim.x * blockDim.x) {
        float4 v; bf162 *dh, *dl;
        if (i < 3 * NZ4) {
            const int e = i / NZ4, j = i - e * NZ4;
            v = (e == 0 ? za : e == 1 ? zb : zc)[j];
            dh = (bf162*)&g_Zh[e][0][0] + (size_t)j * 2;
            dl = (bf162*)&g_Zl[e][0][0] + (size_t)j * 2;
        } else {
            const int k = i - 3 * NZ4;
            const int w = k / NW4, j = k - w * NW4;
            const float4* src = w == 0 ? w0 : w == 1 ? w1 : w == 2 ? w2 : w == 3 ? w3 : w == 4 ? w4 : w5;
            v = src[j];
            dh = (bf162*)&g_Wh[w][0][0] + (size_t)j * 2;
            dl = (bf162*)&g_Wl[w][0][0] + (size_t)j * 2;
        }
        bf16 hx = __float2bfloat16(v.x), hy = __float2bfloat16(v.y);
        bf16 hz = __float2bfloat16(v.z), hw = __float2bfloat16(v.w);
        bf162 p0; p0.x = hx; p0.y = hy;
        bf162 p1; p1.x = hz; p1.y = hw;
        dh[0] = p0; dh[1] = p1;
        bf162 q0; q0.x = __float2bfloat16(v.x - __bfloat162float(hx));
                  q0.y = __float2bfloat16(v.y - __bfloat162float(hy));
        bf162 q1; q1.x = __float2bfloat16(v.z - __bfloat162float(hz));
                  q1.y = __float2bfloat16(v.w - __bfloat162float(hw));
        dl[0] = q0; dl[1] = q1;
    }
}

// =====================================================================
// Projection GEMM via bf16-split MMA (unchanged from R2 known-good).
// =====================================================================
__global__ __launch_bounds__(256, 1)
void proj_mma(const int* __restrict__ idx, int isQ)
{
    const int e = blockIdx.z;
    const int m0 = blockIdx.x * 128, n0 = blockIdx.y * 128;
    const bf16* Zh = &g_Zh[e][0][0];
    const bf16* Zl = &g_Zl[e][0][0];
    const int widx = (isQ ? 3 : 0) + e;
    const bf16* Wh = &g_Wh[widx][0][0];
    const bf16* Wl = &g_Wl[widx][0][0];
    bf16* Ch = isQ ? &g_Qh[e][0][0] : &g_Kh[e][0][0];
    bf16* Cl = isQ ? &g_Ql[e][0][0] : &g_Kl[e][0][0];

    extern __shared__ char sm[];
    const int ASZ = 128 * 40;
    const int BSZ = 32 * 136;
    bf16* sAh = (bf16*)sm;
    bf16* sAl = sAh + 2 * ASZ;
    bf16* sBh = sAl + 2 * ASZ;
    bf16* sBl = sBh + 2 * BSZ;

    const int tid = threadIdx.x;
    const int lane = tid & 31, warp = tid >> 5;
    const int wm = warp >> 2, wn = warp & 3;

    const int l0 = tid, l1 = tid + 256;
    const int ar0 = l0 >> 2, ac0 = (l0 & 3) << 3;
    const int ar1 = l1 >> 2, ac1 = (l1 & 3) << 3;
    const int gr0 = isQ ? idx[m0 + ar0] : (m0 + ar0);
    const int gr1 = isQ ? idx[m0 + ar1] : (m0 + ar1);
    const bf16* pAh0 = Zh + (size_t)gr0 * DM + ac0;
    const bf16* pAh1 = Zh + (size_t)gr1 * DM + ac1;
    const bf16* pAl0 = Zl + (size_t)gr0 * DM + ac0;
    const bf16* pAl1 = Zl + (size_t)gr1 * DM + ac1;

    const int br0 = l0 >> 4, bc0 = (l0 & 15) << 3;
    const int br1 = l1 >> 4, bc1 = (l1 & 15) << 3;
    const bf16* pBh0 = Wh + (size_t)br0 * HD + n0 + bc0;
    const bf16* pBh1 = Wh + (size_t)br1 * HD + n0 + bc1;
    const bf16* pBl0 = Wl + (size_t)br0 * HD + n0 + bc0;
    const bf16* pBl1 = Wl + (size_t)br1 * HD + n0 + bc1;

    float acc[4][4][4];
    #pragma unroll
    for (int i = 0; i < 4; i++)
        #pragma unroll
        for (int j = 0; j < 4; j++)
            #pragma unroll
            for (int k = 0; k < 4; k++) acc[i][j][k] = 0.f;

    {
        *(uint4*)&sAh[ar0 * 40 + ac0] = *(const uint4*)(pAh0);
        *(uint4*)&sAh[ar1 * 40 + ac1] = *(const uint4*)(pAh1);
        *(uint4*)&sAl[ar0 * 40 + ac0] = *(const uint4*)(pAl0);
        *(uint4*)&sAl[ar1 * 40 + ac1] = *(const uint4*)(pAl1);
        *(uint4*)&sBh[br0 * 136 + bc0] = *(const uint4*)(pBh0);
        *(uint4*)&sBh[br1 * 136 + bc1] = *(const uint4*)(pBh1);
        *(uint4*)&sBl[br0 * 136 + bc0] = *(const uint4*)(pBl0);
        *(uint4*)&sBl[br1 * 136 + bc1] = *(const uint4*)(pBl1);
    }
    __syncthreads();

    int cur = 0;
    for (int kt = 0; kt < 16; kt++) {
        uint4 nAh0, nAh1, nAl0, nAl1, nBh0, nBh1, nBl0, nBl1;
        if (kt < 15) {
            const int k0 = (kt + 1) * 32;
            nAh0 = *(const uint4*)(pAh0 + k0);
            nAh1 = *(const uint4*)(pAh1 + k0);
            nAl0 = *(const uint4*)(pAl0 + k0);
            nAl1 = *(const uint4*)(pAl1 + k0);
            nBh0 = *(const uint4*)(pBh0 + (size_t)k0 * HD);
            nBh1 = *(const uint4*)(pBh1 + (size_t)k0 * HD);
            nBl0 = *(const uint4*)(pBl0 + (size_t)k0 * HD);
            nBl1 = *(const uint4*)(pBl1 + (size_t)k0 * HD);
        }

        const bf16* cAh = sAh + cur * ASZ;
        const bf16* cAl = sAl + cur * ASZ;
        const bf16* cBh = sBh + cur * BSZ;
        const bf16* cBl = sBl + cur * BSZ;

        #pragma unroll
        for (int kk = 0; kk < 32; kk += 16) {
            uint32_t ah[4][4], al[4][4], bh[4][2], bl[4][2];
            #pragma unroll
            for (int mi = 0; mi < 4; mi++) {
                const int row = wm * 64 + mi * 16 + (lane & 15);
                const int col = kk + ((lane >> 4) << 3);
                ldsm4(ah[mi], s2u(&cAh[row * 40 + col]));
                ldsm4(al[mi], s2u(&cAl[row * 40 + col]));
            }
            #pragma unroll
            for (int n16 = 0; n16 < 2; n16++) {
                const int row = kk + (lane & 15);
                const int col = wn * 32 + n16 * 16 + ((lane >> 4) << 3);
                uint32_t th[4], tl[4];
                ldsm4t(th, s2u(&cBh[row * 136 + col]));
                ldsm4t(tl, s2u(&cBl[row * 136 + col]));
                bh[n16 * 2 + 0][0] = th[0]; bh[n16 * 2 + 0][1] = th[1];
                bh[n16 * 2 + 1][0] = th[2]; bh[n16 * 2 + 1][1] = th[3];
                bl[n16 * 2 + 0][0] = tl[0]; bl[n16 * 2 + 0][1] = tl[1];
                bl[n16 * 2 + 1][0] = tl[2]; bl[n16 * 2 + 1][1] = tl[3];
            }
            #pragma unroll
            for (int mi = 0; mi < 4; mi++)
                #pragma unroll
                for (int nf = 0; nf < 4; nf++) {
                    mma_bf16(acc[mi][nf], ah[mi], bh[nf]);
                    mma_bf16(acc[mi][nf], ah[mi], bl[nf]);
                    mma_bf16(acc[mi][nf], al[mi], bh[nf]);
                }
        }

        if (kt < 15) {
            const int nb = cur ^ 1;
            *(uint4*)&sAh[nb * ASZ + ar0 * 40 + ac0] = nAh0;
            *(uint4*)&sAh[nb * ASZ + ar1 * 40 + ac1] = nAh1;
            *(uint4*)&sAl[nb * ASZ + ar0 * 40 + ac0] = nAl0;
            *(uint4*)&sAl[nb * ASZ + ar1 * 40 + ac1] = nAl1;
            *(uint4*)&sBh[nb * BSZ + br0 * 136 + bc0] = nBh0;
            *(uint4*)&sBh[nb * BSZ + br1 * 136 + bc1] = nBh1;
            *(uint4*)&sBl[nb * BSZ + br0 * 136 + bc0] = nBl0;
            *(uint4*)&sBl[nb * BSZ + br1 * 136 + bc1] = nBl1;
            __syncthreads();
            cur ^= 1;
        }
    }

    #pragma unroll
    for (int mi = 0; mi < 4; mi++) {
        const int r0 = m0 + wm * 64 + mi * 16 + (lane >> 2);
        #pragma unroll
        for (int nf = 0; nf < 4; nf++) {
            const int cc = n0 + wn * 32 + nf * 8 + ((lane & 3) << 1);
            #pragma unroll
            for (int rh = 0; rh < 2; rh++) {
                const int r = r0 + rh * 8;
                const float x0 = acc[mi][nf][rh * 2 + 0];
                const float x1 = acc[mi][nf][rh * 2 + 1];
                bf162 hp; hp.x = __float2bfloat16(x0); hp.y = __float2bfloat16(x1);
                bf162 lp; lp.x = __float2bfloat16(x0 - __bfloat162float(hp.x));
                          lp.y = __float2bfloat16(x1 - __bfloat162float(hp.y));
                *(bf162*)&Ch[(size_t)r * HD + cc] = hp;
                *(bf162*)&Cl[(size_t)r * HD + cc] = lp;
            }
        }
    }
}

// =====================================================================
// Fused scores + gate + softmax partials + means.
// CTA 64t x 64g, 256 threads (8 warps, wt=warp>>2 in {0,1}, wg=warp&3).
// All 3 evidences staged per h; cp.async double-buffered across h.
// Mean accumulators live in registers (fragment ownership h-invariant).
// =====================================================================
#define MATS   9216                  // 64*72*2 bytes per staged matrix
#define BUFSZ  (12 * MATS)           // Q(6) + K(6)
#define SPARTS 0                     // float2[64][4] = 2048
#define STILES 2048

__global__ __launch_bounds__(256, 1)
void score_cp(const float* __restrict__ gateW, const float* __restrict__ gateB,
              float* __restrict__ out_umean, float* __restrict__ out_amean)
{
    extern __shared__ char sm[];
    float2* parts = (float2*)(sm + SPARTS);

    const int tid = threadIdx.x;
    const int lane = tid & 31, warp = tid >> 5;
    const int wt = warp >> 2, wg = warp & 3;
    const int t0 = blockIdx.x * 64;
    const int g0 = blockIdx.y * 64;

    float acc_u[16];
    float acc_a[3][16];
    #pragma unroll
    for (int i = 0; i < 16; i++) {
        acc_u[i] = 0.f; acc_a[0][i] = 0.f; acc_a[1][i] = 0.f; acc_a[2][i] = 0.f;
    }

    // tile prefetch: 12 matrices of 64x64 bf16 (Q e/hl: 0-5, K e/hl: 6-11)
    auto prefetch = [&](int h, int b) {
        char* base = sm + STILES + b * BUFSZ;
        #pragma unroll
        for (int e = 0; e < 3; e++) {
            const bf16* srcs[4] = { &g_Qh[e][0][0], &g_Ql[e][0][0],
                                    &g_Kh[e][0][0], &g_Kl[e][0][0] };
            #pragma unroll
            for (int v = 0; v < 4; v++) {
                const int m = (v < 2) ? (e * 2 + v) : (6 + e * 2 + (v - 2));
                const int rbase = (v < 2) ? t0 : g0;
                char* mb = base + m * MATS;
                #pragma unroll
                for (int j = 0; j < 2; j++) {
                    const int lin = tid + j * 256;
                    const int row = lin >> 3, c8 = (lin & 7) << 3;
                    cpa16(s2u(mb + (row * 72 + c8) * 2),
                          srcs[v] + (size_t)(rbase + row) * HD + h * DK + c8);
                }
            }
        }
    };

    prefetch(0, 0);
    CP_COMMIT();

    for (int h = 0; h < NH; h++) {
        const int b = h & 1;
        CP_WAIT0();
        __syncthreads();
        if (h < NH - 1) { prefetch(h + 1, b ^ 1); CP_COMMIT(); }

        const bf16* tiles = (const bf16*)(sm + STILES + b * BUFSZ);

        float s[3][2][2][4];
        #pragma unroll
        for (int e = 0; e < 3; e++)
            #pragma unroll
            for (int a = 0; a < 2; a++)
                #pragma unroll
                for (int c = 0; c < 2; c++)
                    #pragma unroll
                    for (int k = 0; k < 4; k++) s[e][a][c][k] = 0.f;

        #pragma unroll
        for (int e = 0; e < 3; e++) {
            const bf16* Qh = tiles + (e * 2 + 0) * (MATS / 2);
            const bf16* Ql = tiles + (e * 2 + 1) * (MATS / 2);
            const bf16* Kh = tiles + (6 + e * 2 + 0) * (MATS / 2);
            const bf16* Kl = tiles + (6 + e * 2 + 1) * (MATS / 2);
            #pragma unroll
            for (int kk = 0; kk < 64; kk += 16) {
                uint32_t ah[2][4], al[2][4];
                #pragma unroll
                for (int mi = 0; mi < 2; mi++) {
                    const int row = wt * 32 + mi * 16 + (lane & 15);
                    const int col = kk + ((lane >> 4) << 3);
                    ldsm4(ah[mi], s2u(&Qh[row * 72 + col]));
                    ldsm4(al[mi], s2u(&Ql[row * 72 + col]));
                }
                uint32_t krh[4], krl[4];
                {
                    const int row = wg * 16 + (lane & 15);
                    const int col = kk + ((lane >> 4) << 3);
                    ldsm4(krh, s2u(&Kh[row * 72 + col]));
                    ldsm4(krl, s2u(&Kl[row * 72 + col]));
                }
                uint32_t bh[2][2] = {{krh[0], krh[2]}, {krh[1], krh[3]}};
                uint32_t bl[2][2] = {{krl[0], krl[2]}, {krl[1], krl[3]}};
                #pragma unroll
                for (int mi = 0; mi < 2; mi++)
                    #pragma unroll
                    for (int nf = 0; nf < 2; nf++) {
                        mma_bf16(s[e][mi][nf], ah[mi], bh[nf]);
                        mma_bf16(s[e][mi][nf], ah[mi], bl[nf]);
                        mma_bf16(s[e][mi][nf], al[mi], bh[nf]);
                    }
            }
        }

        // ---- gate + softmax-stats epilogue ----
        const float w00 = gateW[h*9+0], w01 = gateW[h*9+1], w02 = gateW[h*9+2];
        const float w10 = gateW[h*9+3], w11 = gateW[h*9+4], w12 = gateW[h*9+5];
        const float w20 = gateW[h*9+6], w21 = gateW[h*9+7], w22 = gateW[h*9+8];
        const float gb0 = gateB[h*3+0], gb1 = gateB[h*3+1], gb2 = gateB[h*3+2];

        #pragma unroll
        for (int mi = 0; mi < 2; mi++) {
            #pragma unroll
            for (int rh = 0; rh < 2; rh++) {
                const int tl = wt * 32 + mi * 16 + (lane >> 2) + rh * 8;
                float uv[2][2];
                float um = -1e30f;
                #pragma unroll
                for (int nf = 0; nf < 2; nf++) {
                    #pragma unroll
                    for (int p = 0; p < 2; p++) {
                        const int fi = ((mi * 2 + rh) * 2 + nf) * 2 + p;
                        const float s0 = s[0][mi][nf][rh * 2 + p] * 0.125f;
                        const float s1 = s[1][mi][nf][rh * 2 + p] * 0.125f;
                        const float s2 = s[2][mi][nf][rh * 2 + p] * 0.125f;
                        float l0 = fmaf(s0, w00, fmaf(s1, w10, fmaf(s2, w20, gb0)));
                        float l1 = fmaf(s0, w01, fmaf(s1, w11, fmaf(s2, w21, gb1)));
                        float l2 = fmaf(s0, w02, fmaf(s1, w12, fmaf(s2, w22, gb2)));
                        const float mx = fmaxf(l0, fmaxf(l1, l2));
                        const float e0 = __expf(l0 - mx);
                        const float e1 = __expf(l1 - mx);
                        const float e2 = __expf(l2 - mx);
                        const float inv = 1.0f / (e0 + e1 + e2);
                        const float a0 = e0 * inv, a1 = e1 * inv, a2 = e2 * inv;
                        const float u = fmaf(a0, s0, fmaf(a1, s1, a2 * s2));
                        uv[nf][p] = u;
                        acc_u[fi] += u;
                        acc_a[0][fi] += a0; acc_a[1][fi] += a1; acc_a[2][fi] += a2;
                        um = fmaxf(um, u);
                    }
                }
                um = fmaxf(um, __shfl_xor_sync(0xffffffffu, um, 1));
                um = fmaxf(um, __shfl_xor_sync(0xffffffffu, um, 2));
                float zs = __expf(uv[0][0] - um) + __expf(uv[0][1] - um)
                         + __expf(uv[1][0] - um) + __expf(uv[1][1] - um);
                zs += __shfl_xor_sync(0xffffffffu, zs, 1);
                zs += __shfl_xor_sync(0xffffffffu, zs, 2);
                if ((lane & 3) == 0) parts[tl * 4 + wg] = make_float2(um, zs);
                #pragma unroll
                for (int nf = 0; nf < 2; nf++) {
                    float2 st; st.x = uv[nf][0]; st.y = uv[nf][1];
                    *(float2*)&g_U[h][t0 + tl][g0 + wg * 16 + nf * 8 + ((lane & 3) << 1)] = st;
                }
            }
        }
        __syncthreads();
        if (tid < 64) {
            float2 p0 = parts[tid * 4 + 0], p1 = parts[tid * 4 + 1];
            float2 p2 = parts[tid * 4 + 2], p3 = parts[tid * 4 + 3];
            float m = fmaxf(fmaxf(p0.x, p1.x), fmaxf(p2.x, p3.x));
            float z = p0.y * __expf(p0.x - m) + p1.y * __expf(p1.x - m)
                    + p2.y * __expf(p2.x - m) + p3.y * __expf(p3.x - m);
            g_part[h][t0 + tid][blockIdx.y] = make_float2(m, z);
        }
    }

    // means from register accumulators
    #pragma unroll
    for (int mi = 0; mi < 2; mi++) {
        #pragma unroll
        for (int rh = 0; rh < 2; rh++) {
            const int tl = wt * 32 + mi * 16 + (lane >> 2) + rh * 8;
            #pragma unroll
            for (int nf = 0; nf < 2; nf++) {
                const int gl = wg * 16 + nf * 8 + ((lane & 3) << 1);
                const size_t o = (size_t)(t0 + tl) * NG + g0 + gl;
                const int f0 = ((mi * 2 + rh) * 2 + nf) * 2;
                float2 uo; uo.x = acc_u[f0] * 0.125f; uo.y = acc_u[f0 + 1] * 0.125f;
                *(float2*)&out_umean[o] = uo;
                #pragma unroll
                for (int p = 0; p < 2; p++) {
                    out_amean[(o + p) * 3 + 0] = acc_a[0][f0 + p] * 0.125f;
                    out_amean[(o + p) * 3 + 1] = acc_a[1][f0 + p] * 0.125f;
                    out_amean[(o + p) * 3 + 2] = acc_a[2][f0 + p] * 0.125f;
                }
            }
        }
    }
}

// =====================================================================
// Reduce per-chunk partials -> global (max, 1/Z) per (h, t).
// =====================================================================
__global__ void stats_kernel()
{
    const int gt   = blockIdx.x * blockDim.x + threadIdx.x;
    const int wid  = gt >> 5;
    const int lane = threadIdx.x & 31;
    if (wid >= NH * NT) return;
    const int h = wid >> 9;
    const int t = wid & (NT - 1);

    float2 p[8];
    float m = -1e30f;
    #pragma unroll
    for (int j = 0; j < 8; j++) {
        p[j] = g_part[h][t][lane + 32 * j];
        m = fmaxf(m, p[j].x);
    }
    #pragma unroll
    for (int off = 16; off; off >>= 1)
        m = fmaxf(m, __shfl_xor_sync(0xffffffffu, m, off));
    float z = 0.f;
    #pragma unroll
    for (int j = 0; j < 8; j++) z += p[j].y * __expf(p[j].x - m);
    #pragma unroll
    for (int off = 16; off; off >>= 1)
        z += __shfl_xor_sync(0xffffffffu, z, off);
    if (lane == 0) g_stats[h][t] = make_float2(m, 1.0f / z);
}

// =====================================================================
// A_mean[t,g] = (1/8) * sum_h exp(u[h,t,g] - m[h,t]) / Z[h,t]
// =====================================================================
__global__ void amean_kernel(float* __restrict__ out_A)
{
    const int t = blockIdx.y;
    const int g = blockIdx.x * 256 + threadIdx.x;
    __shared__ float2 st[NH];
    if (threadIdx.x < NH) st[threadIdx.x] = g_stats[threadIdx.x][t];
    __syncthreads();
    float acc = 0.f;
    #pragma unroll
    for (int h = 0; h < NH; h++)
        acc += __expf(g_U[h][t][g] - st[h].x) * st[h].y;
    out_A[(size_t)t * NG + g] = acc * 0.125f;
}

// =====================================================================
__global__ void copy_kernel(const float4* __restrict__ a, const float4* __restrict__ b,
                            float4* __restrict__ out)
{
    const int NA   = (NT * DM) / 4;
    const int NTOT = NA + (NG * DM) / 4;
    for (int i = blockIdx.x * blockDim.x + threadIdx.x; i < NTOT; i += gridDim.x * blockDim.x)
        out[i] = (i < NA) ? a[i] : b[i - NA];
}

// =====================================================================
extern "C" void kernel_launch(void* const* d_in, const int* in_sizes, int n_in,
                              void* d_out, int out_size)
{
    const float* H_TF   = (const float*)d_in[0];
    const float* H_G    = (const float*)d_in[1];
    const float* z_exp  = (const float*)d_in[2];
    const float* z_seq  = (const float*)d_in[3];
    const float* z_txt  = (const float*)d_in[4];
    const int*   tf_idx = (const int*)  d_in[5];
    const float* Wq_seq = (const float*)d_in[6];
    const float* Wk_seq = (const float*)d_in[7];
    const float* Wq_exp = (const float*)d_in[8];
    const float* Wk_exp = (const float*)d_in[9];
    const float* Wq_txt = (const float*)d_in[10];
    const float* Wk_txt = (const float*)d_in[11];
    const float* gateW  = (const float*)d_in[12];
    const float* gateB  = (const float*)d_in[13];
    float* out = (float*)d_out;

    float* out_A  = out + (size_t)NT * DM + (size_t)NG * DM;
    float* out_u  = out_A + (size_t)NT * NG;
    float* out_al = out_u + (size_t)NT * NG;

    const int SCORE_SMEM = STILES + 2 * BUFSZ;   // 2048 + 221184 = 223232
    cudaFuncSetAttribute(proj_mma, cudaFuncAttributeMaxDynamicSharedMemorySize, 75776);
    cudaFuncSetAttribute(score_cp, cudaFuncAttributeMaxDynamicSharedMemorySize, SCORE_SMEM);

    // evidence order: e0 = seq (bind), e1 = exp (coexpr), e2 = txt (know)
    split_kernel<<<4096, 256>>>((const float4*)z_seq, (const float4*)z_exp, (const float4*)z_txt,
                                (const float4*)Wk_seq, (const float4*)Wk_exp, (const float4*)Wk_txt,
                                (const float4*)Wq_seq, (const float4*)Wq_exp, (const float4*)Wq_txt);

    proj_mma<<<dim3(NG / 128, 4, 3), 256, 75776>>>(nullptr, 0);
    proj_mma<<<dim3(NT / 128, 4, 3), 256, 75776>>>(tf_idx, 1);

    score_cp<<<dim3(NT / 64, NG / 64), 256, SCORE_SMEM>>>(gateW, gateB, out_u, out_al);

    stats_kernel<<<(NH * NT * 32) / 256, 256>>>();

    amean_kernel<<<dim3(NG / 256, NT), 256>>>(out_A);

    copy_kernel<<<2048, 256>>>((const float4*)H_TF, (const float4*)H_G, (float4*)out);
}

// round 5
// speedup vs baseline: 2.3143x; 1.0090x over previous
#include <cuda_runtime.h>
#include <cuda_bf16.h>
#include <cstdint>
#include <cstddef>

#define NT 512
#define NG 16384
#define DM 512
#define NH 8
#define DK 64
#define HD 512
#define NGC 256   // NG / 64

typedef __nv_bfloat16 bf16;
typedef __nv_bfloat162 bf162;

// ---------------- scratch (static device memory) ----------------
__device__ bf16  g_Zh[3][NG][DM], g_Zl[3][NG][DM];   // split inputs
__device__ bf16  g_Wh[6][DM][HD], g_Wl[6][DM][HD];   // 0-2: Wk_{seq,exp,txt}, 3-5: Wq_*
__device__ bf16  g_Qh[3][NT][HD], g_Ql[3][NT][HD];
__device__ bf16  g_Kh[3][NG][HD], g_Kl[3][NG][HD];
__device__ float g_U[NH][NT][NG];                    // u scores (fp32)
__device__ float2 g_part[NH][NT][NGC];
__device__ float2 g_stats[NH][NT];

// ---------------- ptx helpers ----------------
__device__ __forceinline__ uint32_t s2u(const void* p) {
    return (uint32_t)__cvta_generic_to_shared(p);
}
__device__ __forceinline__ void ldsm4(uint32_t* r, uint32_t a) {
    asm volatile("ldmatrix.sync.aligned.m8n8.x4.shared.b16 {%0,%1,%2,%3},[%4];\n"
                 : "=r"(r[0]), "=r"(r[1]), "=r"(r[2]), "=r"(r[3]) : "r"(a));
}
__device__ __forceinline__ void ldsm4t(uint32_t* r, uint32_t a) {
    asm volatile("ldmatrix.sync.aligned.m8n8.x4.trans.shared.b16 {%0,%1,%2,%3},[%4];\n"
                 : "=r"(r[0]), "=r"(r[1]), "=r"(r[2]), "=r"(r[3]) : "r"(a));
}
__device__ __forceinline__ void mma_bf16(float* d, const uint32_t* a, const uint32_t* b) {
    asm volatile("mma.sync.aligned.m16n8k16.row.col.f32.bf16.bf16.f32 "
                 "{%0,%1,%2,%3},{%4,%5,%6,%7},{%8,%9},{%0,%1,%2,%3};\n"
                 : "+f"(d[0]), "+f"(d[1]), "+f"(d[2]), "+f"(d[3])
                 : "r"(a[0]), "r"(a[1]), "r"(a[2]), "r"(a[3]), "r"(b[0]), "r"(b[1]));
}
__device__ __forceinline__ void cpa16(uint32_t s, const void* g) {
    asm volatile("cp.async.cg.shared.global [%0], [%1], 16;\n" :: "r"(s), "l"(g) : "memory");
}
#define CP_COMMIT() asm volatile("cp.async.commit_group;\n" ::: "memory")
#define CP_WAIT0()  asm volatile("cp.async.wait_group 0;\n" ::: "memory")

// =====================================================================
// Split fp32 -> bf16 hi/lo pairs for z (3) and W (6).
// =====================================================================
__global__ void split_kernel(const float4* __restrict__ za, const float4* __restrict__ zb,
                             const float4* __restrict__ zc,
                             const float4* __restrict__ w0, const float4* __restrict__ w1,
                             const float4* __restrict__ w2, const float4* __restrict__ w3,
                             const float4* __restrict__ w4, const float4* __restrict__ w5)
{
    const int NZ4 = NG * DM / 4;
    const int NW4 = DM * HD / 4;
    const int TOT = 3 * NZ4 + 6 * NW4;
    for (int i = blockIdx.x * blockDim.x + threadIdx.x; i < TOT; i += gridDim.x * blockDim.x) {
        float4 v; bf162 *dh, *dl;
        if (i < 3 * NZ4) {
            const int e = i / NZ4, j = i - e * NZ4;
            v = (e == 0 ? za : e == 1 ? zb : zc)[j];
            dh = (bf162*)&g_Zh[e][0][0] + (size_t)j * 2;
            dl = (bf162*)&g_Zl[e][0][0] + (size_t)j * 2;
        } else {
            const int k = i - 3 * NZ4;
            const int w = k / NW4, j = k - w * NW4;
            const float4* src = w == 0 ? w0 : w == 1 ? w1 : w == 2 ? w2 : w == 3 ? w3 : w == 4 ? w4 : w5;
            v = src[j];
            dh = (bf162*)&g_Wh[w][0][0] + (size_t)j * 2;
            dl = (bf162*)&g_Wl[w][0][0] + (size_t)j * 2;
        }
        bf16 hx = __float2bfloat16(v.x), hy = __float2bfloat16(v.y);
        bf16 hz = __float2bfloat16(v.z), hw = __float2bfloat16(v.w);
        bf162 p0; p0.x = hx; p0.y = hy;
        bf162 p1; p1.x = hz; p1.y = hw;
        dh[0] = p0; dh[1] = p1;
        bf162 q0; q0.x = __float2bfloat16(v.x - __bfloat162float(hx));
                  q0.y = __float2bfloat16(v.y - __bfloat162float(hy));
        bf162 q1; q1.x = __float2bfloat16(v.z - __bfloat162float(hz));
                  q1.y = __float2bfloat16(v.w - __bfloat162float(hw));
        dl[0] = q0; dl[1] = q1;
    }
}

// =====================================================================
// Projection GEMM via bf16-split MMA, cp.async double-buffered.
// CTA 128x128, BK=32, 256 threads (8 warps, 2x4), warp 64x32.
// =====================================================================
__global__ __launch_bounds__(256, 1)
void proj_mma(const int* __restrict__ idx, int isQ)
{
    const int e = blockIdx.z;
    const int m0 = blockIdx.x * 128, n0 = blockIdx.y * 128;
    const bf16* Zh = &g_Zh[e][0][0];
    const bf16* Zl = &g_Zl[e][0][0];
    const int widx = (isQ ? 3 : 0) + e;
    const bf16* Wh = &g_Wh[widx][0][0];
    const bf16* Wl = &g_Wl[widx][0][0];
    bf16* Ch = isQ ? &g_Qh[e][0][0] : &g_Kh[e][0][0];
    bf16* Cl = isQ ? &g_Ql[e][0][0] : &g_Kl[e][0][0];

    extern __shared__ char sm[];
    const int ASZ = 128 * 40;   // elements
    const int BSZ = 32 * 136;
    bf16* sAh = (bf16*)sm;
    bf16* sAl = sAh + 2 * ASZ;
    bf16* sBh = sAl + 2 * ASZ;
    bf16* sBl = sBh + 2 * BSZ;

    const int tid = threadIdx.x;
    const int lane = tid & 31, warp = tid >> 5;
    const int wm = warp >> 2, wn = warp & 3;

    // loader geometry (2 ops/thread per matrix)
    const int l0 = tid, l1 = tid + 256;
    const int ar0 = l0 >> 2, ac0 = (l0 & 3) << 3;
    const int ar1 = l1 >> 2, ac1 = (l1 & 3) << 3;
    const int gr0 = isQ ? idx[m0 + ar0] : (m0 + ar0);
    const int gr1 = isQ ? idx[m0 + ar1] : (m0 + ar1);
    const int br0 = l0 >> 4, bc0 = (l0 & 15) << 3;
    const int br1 = l1 >> 4, bc1 = (l1 & 15) << 3;

    auto prefetch = [&](int kt, int b) {
        const int k0 = kt * 32;
        cpa16(s2u(&sAh[b * ASZ + ar0 * 40 + ac0]), Zh + (size_t)gr0 * DM + k0 + ac0);
        cpa16(s2u(&sAh[b * ASZ + ar1 * 40 + ac1]), Zh + (size_t)gr1 * DM + k0 + ac1);
        cpa16(s2u(&sAl[b * ASZ + ar0 * 40 + ac0]), Zl + (size_t)gr0 * DM + k0 + ac0);
        cpa16(s2u(&sAl[b * ASZ + ar1 * 40 + ac1]), Zl + (size_t)gr1 * DM + k0 + ac1);
        cpa16(s2u(&sBh[b * BSZ + br0 * 136 + bc0]), Wh + (size_t)(k0 + br0) * HD + n0 + bc0);
        cpa16(s2u(&sBh[b * BSZ + br1 * 136 + bc1]), Wh + (size_t)(k0 + br1) * HD + n0 + bc1);
        cpa16(s2u(&sBl[b * BSZ + br0 * 136 + bc0]), Wl + (size_t)(k0 + br0) * HD + n0 + bc0);
        cpa16(s2u(&sBl[b * BSZ + br1 * 136 + bc1]), Wl + (size_t)(k0 + br1) * HD + n0 + bc1);
    };

    float acc[4][4][4];
    #pragma unroll
    for (int i = 0; i < 4; i++)
        #pragma unroll
        for (int j = 0; j < 4; j++)
            #pragma unroll
            for (int k = 0; k < 4; k++) acc[i][j][k] = 0.f;

    prefetch(0, 0);
    CP_COMMIT();
    CP_WAIT0();
    __syncthreads();

    int cur = 0;
    for (int kt = 0; kt < 16; kt++) {
        if (kt < 15) { prefetch(kt + 1, cur ^ 1); CP_COMMIT(); }

        const bf16* cAh = sAh + cur * ASZ;
        const bf16* cAl = sAl + cur * ASZ;
        const bf16* cBh = sBh + cur * BSZ;
        const bf16* cBl = sBl + cur * BSZ;

        #pragma unroll
        for (int kk = 0; kk < 32; kk += 16) {
            uint32_t ah[4][4], al[4][4], bh[4][2], bl[4][2];
            #pragma unroll
            for (int mi = 0; mi < 4; mi++) {
                const int row = wm * 64 + mi * 16 + (lane & 15);
                const int col = kk + ((lane >> 4) << 3);
                ldsm4(ah[mi], s2u(&cAh[row * 40 + col]));
                ldsm4(al[mi], s2u(&cAl[row * 40 + col]));
            }
            #pragma unroll
            for (int n16 = 0; n16 < 2; n16++) {
                const int row = kk + (lane & 15);
                const int col = wn * 32 + n16 * 16 + ((lane >> 4) << 3);
                uint32_t th[4], tl[4];
                ldsm4t(th, s2u(&cBh[row * 136 + col]));
                ldsm4t(tl, s2u(&cBl[row * 136 + col]));
                bh[n16 * 2 + 0][0] = th[0]; bh[n16 * 2 + 0][1] = th[1];
                bh[n16 * 2 + 1][0] = th[2]; bh[n16 * 2 + 1][1] = th[3];
                bl[n16 * 2 + 0][0] = tl[0]; bl[n16 * 2 + 0][1] = tl[1];
                bl[n16 * 2 + 1][0] = tl[2]; bl[n16 * 2 + 1][1] = tl[3];
            }
            #pragma unroll
            for (int mi = 0; mi < 4; mi++)
                #pragma unroll
                for (int nf = 0; nf < 4; nf++) {
                    mma_bf16(acc[mi][nf], ah[mi], bh[nf]);
                    mma_bf16(acc[mi][nf], ah[mi], bl[nf]);
                    mma_bf16(acc[mi][nf], al[mi], bh[nf]);
                }
        }

        if (kt < 15) {
            CP_WAIT0();
            __syncthreads();
            cur ^= 1;
        }
    }

    #pragma unroll
    for (int mi = 0; mi < 4; mi++) {
        const int r0 = m0 + wm * 64 + mi * 16 + (lane >> 2);
        #pragma unroll
        for (int nf = 0; nf < 4; nf++) {
            const int cc = n0 + wn * 32 + nf * 8 + ((lane & 3) << 1);
            #pragma unroll
            for (int rh = 0; rh < 2; rh++) {
                const int r = r0 + rh * 8;
                const float x0 = acc[mi][nf][rh * 2 + 0];
                const float x1 = acc[mi][nf][rh * 2 + 1];
                bf162 hp; hp.x = __float2bfloat16(x0); hp.y = __float2bfloat16(x1);
                bf162 lp; lp.x = __float2bfloat16(x0 - __bfloat162float(hp.x));
                          lp.y = __float2bfloat16(x1 - __bfloat162float(hp.y));
                *(bf162*)&Ch[(size_t)r * HD + cc] = hp;
                *(bf162*)&Cl[(size_t)r * HD + cc] = lp;
            }
        }
    }
}

// =====================================================================
// Fused scores + gate + softmax partials + means.
// CTA 64t x 64g, 512 threads (16 warps: wt=warp>>2 in 0..3, wg=warp&3).
// Warp tile 16t x 16g. All 3 evidences staged per h; cp.async double-buffer.
// alpha2 reconstructed as 1 - alpha0 - alpha1 at writeout.
// =====================================================================
#define MATS   9216                  // 64*72*2 bytes per staged matrix
#define BUFSZ  (12 * MATS)           // Q(6) + K(6)
#define SPARTS 0                     // float2[64][4] = 2048
#define STILES 2048

__global__ __launch_bounds__(512, 1)
void score_cp(const float* __restrict__ gateW, const float* __restrict__ gateB,
              float* __restrict__ out_umean, float* __restrict__ out_amean)
{
    extern __shared__ char sm[];
    float2* parts = (float2*)(sm + SPARTS);

    const int tid = threadIdx.x;
    const int lane = tid & 31, warp = tid >> 5;
    const int wt = warp >> 2, wg = warp & 3;
    const int t0 = blockIdx.x * 64;
    const int g0 = blockIdx.y * 64;

    float acc_u[8], acc_a0[8], acc_a1[8];
    #pragma unroll
    for (int i = 0; i < 8; i++) { acc_u[i] = 0.f; acc_a0[i] = 0.f; acc_a1[i] = 0.f; }

    // 12 matrices of 64x64 bf16 (Q e/hl: 0-5, K e/hl: 6-11); 1 op/thread/mat
    const int prow = tid >> 3, pc8 = (tid & 7) << 3;
    auto prefetch = [&](int h, int b) {
        char* base = sm + STILES + b * BUFSZ;
        #pragma unroll
        for (int e = 0; e < 3; e++) {
            const bf16* srcs[4] = { &g_Qh[e][0][0], &g_Ql[e][0][0],
                                    &g_Kh[e][0][0], &g_Kl[e][0][0] };
            #pragma unroll
            for (int v = 0; v < 4; v++) {
                const int m = (v < 2) ? (e * 2 + v) : (6 + e * 2 + (v - 2));
                const int rbase = (v < 2) ? t0 : g0;
                cpa16(s2u(base + m * MATS + (prow * 72 + pc8) * 2),
                      srcs[v] + (size_t)(rbase + prow) * HD + h * DK + pc8);
            }
        }
    };

    prefetch(0, 0);
    CP_COMMIT();

    for (int h = 0; h < NH; h++) {
        const int b = h & 1;
        CP_WAIT0();
        __syncthreads();
        if (h < NH - 1) { prefetch(h + 1, b ^ 1); CP_COMMIT(); }

        const bf16* tiles = (const bf16*)(sm + STILES + b * BUFSZ);

        float s[3][2][4];
        #pragma unroll
        for (int e = 0; e < 3; e++)
            #pragma unroll
            for (int c = 0; c < 2; c++)
                #pragma unroll
                for (int k = 0; k < 4; k++) s[e][c][k] = 0.f;

        #pragma unroll
        for (int e = 0; e < 3; e++) {
            const bf16* Qh = tiles + (e * 2 + 0) * (MATS / 2);
            const bf16* Ql = tiles + (e * 2 + 1) * (MATS / 2);
            const bf16* Kh = tiles + (6 + e * 2 + 0) * (MATS / 2);
            const bf16* Kl = tiles + (6 + e * 2 + 1) * (MATS / 2);
            #pragma unroll
            for (int kk = 0; kk < 64; kk += 16) {
                const int col = kk + ((lane >> 4) << 3);
                uint32_t ah[4], al[4];
                {
                    const int row = wt * 16 + (lane & 15);
                    ldsm4(ah, s2u(&Qh[row * 72 + col]));
                    ldsm4(al, s2u(&Ql[row * 72 + col]));
                }
                uint32_t krh[4], krl[4];
                {
                    const int row = wg * 16 + (lane & 15);
                    ldsm4(krh, s2u(&Kh[row * 72 + col]));
                    ldsm4(krl, s2u(&Kl[row * 72 + col]));
                }
                uint32_t bh[2][2] = {{krh[0], krh[2]}, {krh[1], krh[3]}};
                uint32_t bl[2][2] = {{krl[0], krl[2]}, {krl[1], krl[3]}};
                #pragma unroll
                for (int nf = 0; nf < 2; nf++) {
                    mma_bf16(s[e][nf], ah, bh[nf]);
                    mma_bf16(s[e][nf], ah, bl[nf]);
                    mma_bf16(s[e][nf], al, bh[nf]);
                }
            }
        }

        // ---- gate + softmax-stats epilogue ----
        const float w00 = gateW[h*9+0], w01 = gateW[h*9+1], w02 = gateW[h*9+2];
        const float w10 = gateW[h*9+3], w11 = gateW[h*9+4], w12 = gateW[h*9+5];
        const float w20 = gateW[h*9+6], w21 = gateW[h*9+7], w22 = gateW[h*9+8];
        const float gb0 = gateB[h*3+0], gb1 = gateB[h*3+1], gb2 = gateB[h*3+2];

        #pragma unroll
        for (int rh = 0; rh < 2; rh++) {
            const int tl = wt * 16 + (lane >> 2) + rh * 8;
            float uv[2][2];
            float um = -1e30f;
            #pragma unroll
            for (int nf = 0; nf < 2; nf++) {
                #pragma unroll
                for (int p = 0; p < 2; p++) {
                    const int fi = rh * 4 + nf * 2 + p;
                    const float s0 = s[0][nf][rh * 2 + p] * 0.125f;
                    const float s1 = s[1][nf][rh * 2 + p] * 0.125f;
                    const float s2 = s[2][nf][rh * 2 + p] * 0.125f;
                    float l0 = fmaf(s0, w00, fmaf(s1, w10, fmaf(s2, w20, gb0)));
                    float l1 = fmaf(s0, w01, fmaf(s1, w11, fmaf(s2, w21, gb1)));
                    float l2 = fmaf(s0, w02, fmaf(s1, w12, fmaf(s2, w22, gb2)));
                    const float mx = fmaxf(l0, fmaxf(l1, l2));
                    const float e0 = __expf(l0 - mx);
                    const float e1 = __expf(l1 - mx);
                    const float e2 = __expf(l2 - mx);
                    const float inv = 1.0f / (e0 + e1 + e2);
                    const float a0 = e0 * inv, a1 = e1 * inv, a2 = e2 * inv;
                    const float u = fmaf(a0, s0, fmaf(a1, s1, a2 * s2));
                    uv[nf][p] = u;
                    acc_u[fi] += u;
                    acc_a0[fi] += a0; acc_a1[fi] += a1;
                    um = fmaxf(um, u);
                }
            }
            um = fmaxf(um, __shfl_xor_sync(0xffffffffu, um, 1));
            um = fmaxf(um, __shfl_xor_sync(0xffffffffu, um, 2));
            float zs = __expf(uv[0][0] - um) + __expf(uv[0][1] - um)
                     + __expf(uv[1][0] - um) + __expf(uv[1][1] - um);
            zs += __shfl_xor_sync(0xffffffffu, zs, 1);
            zs += __shfl_xor_sync(0xffffffffu, zs, 2);
            if ((lane & 3) == 0) parts[tl * 4 + wg] = make_float2(um, zs);
            #pragma unroll
            for (int nf = 0; nf < 2; nf++) {
                float2 st; st.x = uv[nf][0]; st.y = uv[nf][1];
                *(float2*)&g_U[h][t0 + tl][g0 + wg * 16 + nf * 8 + ((lane & 3) << 1)] = st;
            }
        }
        __syncthreads();
        if (tid < 64) {
            float2 p0 = parts[tid * 4 + 0], p1 = parts[tid * 4 + 1];
            float2 p2 = parts[tid * 4 + 2], p3 = parts[tid * 4 + 3];
            float m = fmaxf(fmaxf(p0.x, p1.x), fmaxf(p2.x, p3.x));
            float z = p0.y * __expf(p0.x - m) + p1.y * __expf(p1.x - m)
                    + p2.y * __expf(p2.x - m) + p3.y * __expf(p3.x - m);
            g_part[h][t0 + tid][blockIdx.y] = make_float2(m, z);
        }
    }

    // means from register accumulators
    #pragma unroll
    for (int rh = 0; rh < 2; rh++) {
        const int tl = wt * 16 + (lane >> 2) + rh * 8;
        #pragma unroll
        for (int nf = 0; nf < 2; nf++) {
            const int gl = wg * 16 + nf * 8 + ((lane & 3) << 1);
            const size_t o = (size_t)(t0 + tl) * NG + g0 + gl;
            const int f0 = rh * 4 + nf * 2;
            float2 uo; uo.x = acc_u[f0] * 0.125f; uo.y = acc_u[f0 + 1] * 0.125f;
            *(float2*)&out_umean[o] = uo;
            #pragma unroll
            for (int p = 0; p < 2; p++) {
                const float a0m = acc_a0[f0 + p] * 0.125f;
                const float a1m = acc_a1[f0 + p] * 0.125f;
                out_amean[(o + p) * 3 + 0] = a0m;
                out_amean[(o + p) * 3 + 1] = a1m;
                out_amean[(o + p) * 3 + 2] = 1.0f - a0m - a1m;
            }
        }
    }
}

// =====================================================================
// Reduce per-chunk partials -> global (max, 1/Z) per (h, t).
// =====================================================================
__global__ void stats_kernel()
{
    const int gt   = blockIdx.x * blockDim.x + threadIdx.x;
    const int wid  = gt >> 5;
    const int lane = threadIdx.x & 31;
    if (wid >= NH * NT) return;
    const int h = wid >> 9;
    const int t = wid & (NT - 1);

    float2 p[8];
    float m = -1e30f;
    #pragma unroll
    for (int j = 0; j < 8; j++) {
        p[j] = g_part[h][t][lane + 32 * j];
        m = fmaxf(m, p[j].x);
    }
    #pragma unroll
    for (int off = 16; off; off >>= 1)
        m = fmaxf(m, __shfl_xor_sync(0xffffffffu, m, off));
    float z = 0.f;
    #pragma unroll
    for (int j = 0; j < 8; j++) z += p[j].y * __expf(p[j].x - m);
    #pragma unroll
    for (int off = 16; off; off >>= 1)
        z += __shfl_xor_sync(0xffffffffu, z, off);
    if (lane == 0) g_stats[h][t] = make_float2(m, 1.0f / z);
}

// =====================================================================
// A_mean[t,g] = (1/8) * sum_h exp(u[h,t,g] - m[h,t]) / Z[h,t]
// =====================================================================
__global__ void amean_kernel(float* __restrict__ out_A)
{
    const int t = blockIdx.y;
    const int g = blockIdx.x * 256 + threadIdx.x;
    __shared__ float2 st[NH];
    if (threadIdx.x < NH) st[threadIdx.x] = g_stats[threadIdx.x][t];
    __syncthreads();
    float acc = 0.f;
    #pragma unroll
    for (int h = 0; h < NH; h++)
        acc += __expf(g_U[h][t][g] - st[h].x) * st[h].y;
    out_A[(size_t)t * NG + g] = acc * 0.125f;
}

// =====================================================================
__global__ void copy_kernel(const float4* __restrict__ a, const float4* __restrict__ b,
                            float4* __restrict__ out)
{
    const int NA   = (NT * DM) / 4;
    const int NTOT = NA + (NG * DM) / 4;
    for (int i = blockIdx.x * blockDim.x + threadIdx.x; i < NTOT; i += gridDim.x * blockDim.x)
        out[i] = (i < NA) ? a[i] : b[i - NA];
}

// =====================================================================
extern "C" void kernel_launch(void* const* d_in, const int* in_sizes, int n_in,
                              void* d_out, int out_size)
{
    const float* H_TF   = (const float*)d_in[0];
    const float* H_G    = (const float*)d_in[1];
    const float* z_exp  = (const float*)d_in[2];
    const float* z_seq  = (const float*)d_in[3];
    const float* z_txt  = (const float*)d_in[4];
    const int*   tf_idx = (const int*)  d_in[5];
    const float* Wq_seq = (const float*)d_in[6];
    const float* Wk_seq = (const float*)d_in[7];
    const float* Wq_exp = (const float*)d_in[8];
    const float* Wk_exp = (const float*)d_in[9];
    const float* Wq_txt = (const float*)d_in[10];
    const float* Wk_txt = (const float*)d_in[11];
    const float* gateW  = (const float*)d_in[12];
    const float* gateB  = (const float*)d_in[13];
    float* out = (float*)d_out;

    float* out_A  = out + (size_t)NT * DM + (size_t)NG * DM;
    float* out_u  = out_A + (size_t)NT * NG;
    float* out_al = out_u + (size_t)NT * NG;

    const int SCORE_SMEM = STILES + 2 * BUFSZ;   // 2048 + 221184 = 223232
    cudaFuncSetAttribute(proj_mma, cudaFuncAttributeMaxDynamicSharedMemorySize, 75776);
    cudaFuncSetAttribute(score_cp, cudaFuncAttributeMaxDynamicSharedMemorySize, SCORE_SMEM);

    // evidence order: e0 = seq (bind), e1 = exp (coexpr), e2 = txt (know)
    split_kernel<<<4096, 256>>>((const float4*)z_seq, (const float4*)z_exp, (const float4*)z_txt,
                                (const float4*)Wk_seq, (const float4*)Wk_exp, (const float4*)Wk_txt,
                                (const float4*)Wq_seq, (const float4*)Wq_exp, (const float4*)Wq_txt);

    proj_mma<<<dim3(NG / 128, 4, 3), 256, 75776>>>(nullptr, 0);
    proj_mma<<<dim3(NT / 128, 4, 3), 256, 75776>>>(tf_idx, 1);

    score_cp<<<dim3(NT / 64, NG / 64), 512, SCORE_SMEM>>>(gateW, gateB, out_u, out_al);

    stats_kernel<<<(NH * NT * 32) / 256, 256>>>();

    amean_kernel<<<dim3(NG / 256, NT), 256>>>(out_A);

    copy_kernel<<<2048, 256>>>((const float4*)H_TF, (const float4*)H_G, (float4*)out);
}